// round 5
// baseline (speedup 1.0000x reference)
#include <cuda_runtime.h>

// Gegenbauer (alpha=0.5 -> Legendre) embedding: out[row, i-1] = C_i(x[row]), i=1..64.
// Round 5: stream coefficients to smem 4-at-a-time (immediate STS.128) so no
// 32-float register buffer stays live -> regs ~35 -> smem-limited 12 CTAs/SM.
// Two 32-column passes, padded smem (PAD=9 f4) keeps both STS and LDS
// conflict-free; copy-out warps write full 128B lines.

#define DIM_OUT 64
#define RPB 128          // rows per block == threads
#define HF4 8            // float4 per half-row (32 floats = 128B)
#define PAD 9            // smem row stride in float4

__global__ void __launch_bounds__(RPB) geg_kernel(const float* __restrict__ x,
                                                  float* __restrict__ out,
                                                  int n) {
    __shared__ float4 s[RPB * PAD];   // 18,432 B

    const int tid = threadIdx.x;
    const size_t row = (size_t)blockIdx.x * RPB + tid;
    const float xv = (row < (size_t)n) ? x[row] : 0.0f;

    float4* __restrict__ o4 = reinterpret_cast<float4*>(out);
    const size_t base_f4 = (size_t)blockIdx.x * RPB * (DIM_OUT / 4);
    const size_t total_f4 = ((size_t)n * DIM_OUT) / 4;

    float prev2 = 1.0f;   // C_0
    float prev  = xv;     // C_1 (alpha = 0.5)

    #pragma unroll
    for (int pass = 0; pass < 2; ++pass) {
        // ---- compute 32 coefficients, streaming to smem 4 at a time ----
        #pragma unroll
        for (int g = 0; g < HF4; ++g) {
            float4 v;
            float* vp = reinterpret_cast<float*>(&v);
            #pragma unroll
            for (int e = 0; e < 4; ++e) {
                const int k = pass * 32 + g * 4 + e;   // coeff index: holds C_{k+1}
                float ci;
                if (k == 0) {
                    ci = xv;                            // C_1
                } else {
                    const int i = k + 1;
                    const float A = (float)(2 * i - 1);
                    const float B = (float)(1 - i);
                    const float r = 1.0f / (float)i;
                    ci = (A * xv * prev + B * prev2) * r;
                    prev2 = prev;
                    prev  = ci;
                }
                vp[e] = ci;
            }
            s[tid * PAD + g] = v;   // conflict-free: chunk-group (9*tid+g)%8 distinct per phase
        }
        __syncthreads();

        // ---- coalesced copy-out of this 32-column block ----
        #pragma unroll
        for (int j = 0; j < HF4; ++j) {
            const int f = j * RPB + tid;   // index within 128x8 f4 tile
            const int r = f >> 3;          // row within block
            const int cq = f & 7;          // f4 column within half-row
            const size_t g = base_f4 + (size_t)r * (DIM_OUT / 4) + pass * HF4 + cq;
            if (g < total_f4) o4[g] = s[r * PAD + cq];
        }
        __syncthreads();
    }
}

extern "C" void kernel_launch(void* const* d_in, const int* in_sizes, int n_in,
                              void* d_out, int out_size) {
    const float* x = (const float*)d_in[0];
    float* out = (float*)d_out;
    int n = in_sizes[0];   // 2,000,000 rows
    int blocks = (n + RPB - 1) / RPB;
    geg_kernel<<<blocks, RPB>>>(x, out, n);
}

// round 6
// speedup vs baseline: 1.0024x; 1.0024x over previous
#include <cuda_runtime.h>

// Gegenbauer (alpha=0.5 -> Legendre) embedding: out[row, i-1] = C_i(x[row]), i=1..64.
// Round 6: Round-5 structure + streaming stores (__stcs, evict-first) to smooth
// the L2->DRAM write drain, and no trailing barrier after the final copy-out.

#define DIM_OUT 64
#define RPB 128          // rows per block == threads
#define HF4 8            // float4 per half-row (32 floats = 128B)
#define PAD 9            // smem row stride in float4 (conflict-free phases)

__device__ __forceinline__ void compute32(int pass, float xv, float& prev,
                                          float& prev2, float4* s, int tid) {
    #pragma unroll
    for (int g = 0; g < HF4; ++g) {
        float4 v;
        float* vp = reinterpret_cast<float*>(&v);
        #pragma unroll
        for (int e = 0; e < 4; ++e) {
            const int k = pass * 32 + g * 4 + e;   // slot holds C_{k+1}
            float ci;
            if (k == 0) {
                ci = xv;                            // C_1 (alpha = 0.5)
            } else {
                const int i = k + 1;
                const float A = (float)(2 * i - 1);
                const float B = (float)(1 - i);
                const float r = 1.0f / (float)i;
                ci = (A * xv * prev + B * prev2) * r;
                prev2 = prev;
                prev  = ci;
            }
            vp[e] = ci;
        }
        s[tid * PAD + g] = v;
    }
}

__device__ __forceinline__ void copyout32(int pass, const float4* s, int tid,
                                          float4* o4, size_t base_f4,
                                          size_t total_f4) {
    #pragma unroll
    for (int j = 0; j < HF4; ++j) {
        const int f = j * RPB + tid;   // index within 128x8 f4 tile
        const int r = f >> 3;          // row within block
        const int cq = f & 7;          // f4 column within half-row
        const size_t g = base_f4 + (size_t)r * (DIM_OUT / 4) + pass * HF4 + cq;
        if (g < total_f4) __stcs(&o4[g], s[r * PAD + cq]);   // STG.E.CS (evict-first)
    }
}

__global__ void __launch_bounds__(RPB) geg_kernel(const float* __restrict__ x,
                                                  float* __restrict__ out,
                                                  int n) {
    __shared__ float4 s[RPB * PAD];   // 18,432 B

    const int tid = threadIdx.x;
    const size_t row = (size_t)blockIdx.x * RPB + tid;
    const float xv = (row < (size_t)n) ? __ldcs(&x[row]) : 0.0f;

    float4* __restrict__ o4 = reinterpret_cast<float4*>(out);
    const size_t base_f4 = (size_t)blockIdx.x * RPB * (DIM_OUT / 4);
    const size_t total_f4 = ((size_t)n * DIM_OUT) / 4;

    float prev2 = 1.0f;   // C_0
    float prev  = xv;     // C_1

    // ---- pass 0: C_1..C_32 ----
    compute32(0, xv, prev, prev2, s, tid);
    __syncthreads();
    copyout32(0, s, tid, o4, base_f4, total_f4);
    __syncthreads();                       // guard smem reuse

    // ---- pass 1: C_33..C_64 ----
    compute32(1, xv, prev, prev2, s, tid);
    __syncthreads();
    copyout32(1, s, tid, o4, base_f4, total_f4);
    // no trailing barrier: kernel exit synchronizes
}

extern "C" void kernel_launch(void* const* d_in, const int* in_sizes, int n_in,
                              void* d_out, int out_size) {
    const float* x = (const float*)d_in[0];
    float* out = (float*)d_out;
    int n = in_sizes[0];   // 2,000,000 rows
    int blocks = (n + RPB - 1) / RPB;
    geg_kernel<<<blocks, RPB>>>(x, out, n);
}